// round 2
// baseline (speedup 1.0000x reference)
#include <cuda_runtime.h>
#include <math.h>
#include <stddef.h>

// Problem constants
#define Bc 2
#define Lc 2048
#define Dc 1024
#define Hc 16
#define DKc 64
#define DVc 64
#define Mrows (Bc*Lc)            /* 4096 */

// Scratch (device globals -- no allocation allowed)
__device__ float g_QH[(size_t)Bc*Hc*Lc*DKc];   // [B,H,L,DK]
__device__ float g_KH[(size_t)Bc*Hc*Lc*DKc];
__device__ float g_VH[(size_t)Bc*Hc*Lc*DVc];
__device__ float g_OH[(size_t)Mrows*Hc*DVc];   // [B,L,H*DV]
__device__ float g_OPRE[(size_t)Mrows*Dc];     // pre-LayerNorm

// ---------------------------------------------------------------------------
// Tiled SGEMM: C = A[M,K] @ W[K,N]  (M=4096, N=1024, K=1024)
// MODE 0: scatter epilogue into [B,H,L,64] head layout, multiply by `scale`
// MODE 1: C[m*N+n] = acc + R[m*N+n]   (residual add)
// Block tile 64x64, BK=16, 256 threads, 4x4 per thread.
// ---------------------------------------------------------------------------
template <int MODE>
__global__ void __launch_bounds__(256)
sgemm_k(const float* __restrict__ A, const float* __restrict__ W,
        float* __restrict__ C, const float* __restrict__ R,
        float scale, int K, int N)
{
    __shared__ float As[16][64];   // [k][m]
    __shared__ float Ws[16][64];   // [k][n]

    const int t  = threadIdx.x;
    const int m0 = blockIdx.y * 64;
    const int n0 = blockIdx.x * 64;
    const int tx = t & 15;        // 0..15 -> n
    const int ty = t >> 4;        // 0..15 -> m

    const int arow = t >> 2;            // 0..63
    const int ac4  = (t & 3) * 4;       // 0..12
    const int wrow = t >> 4;            // 0..15
    const int wc4  = (t & 15) * 4;      // 0..60

    float acc[4][4] = {};

    for (int k0 = 0; k0 < K; k0 += 16) {
        float4 av = *(const float4*)&A[(size_t)(m0 + arow) * K + k0 + ac4];
        float4 wv = *(const float4*)&W[(size_t)(k0 + wrow) * N + n0 + wc4];
        __syncthreads();
        As[ac4 + 0][arow] = av.x;
        As[ac4 + 1][arow] = av.y;
        As[ac4 + 2][arow] = av.z;
        As[ac4 + 3][arow] = av.w;
        *(float4*)&Ws[wrow][wc4] = wv;
        __syncthreads();
#pragma unroll
        for (int kk = 0; kk < 16; kk++) {
            float4 a4 = *(const float4*)&As[kk][ty * 4];
            float4 b4 = *(const float4*)&Ws[kk][tx * 4];
            float a[4] = {a4.x, a4.y, a4.z, a4.w};
            float b[4] = {b4.x, b4.y, b4.z, b4.w};
#pragma unroll
            for (int i = 0; i < 4; i++)
#pragma unroll
                for (int j = 0; j < 4; j++) acc[i][j] += a[i] * b[j];
        }
    }

    if (MODE == 0) {
#pragma unroll
        for (int i = 0; i < 4; i++) {
            int m  = m0 + ty * 4 + i;
            int b_ = m >> 11;               // / L
            int l  = m & (Lc - 1);
#pragma unroll
            for (int j = 0; j < 4; j++) {
                int n  = n0 + tx * 4 + j;
                int h  = n >> 6;
                int dk = n & 63;
                C[(((size_t)b_ * Hc + h) * Lc + l) * 64 + dk] = acc[i][j] * scale;
            }
        }
    } else {
#pragma unroll
        for (int i = 0; i < 4; i++) {
            int m = m0 + ty * 4 + i;
#pragma unroll
            for (int j = 0; j < 4; j++) {
                int n = n0 + tx * 4 + j;
                C[(size_t)m * N + n] = acc[i][j] + R[(size_t)m * N + n];
            }
        }
    }
}

// ---------------------------------------------------------------------------
// Fused attention: per block = 16 queries of one (b,h).
// Full 2048-key score row kept in smem -> masked softmax in-place ->
// optional attn write (once) -> P@V from smem.
// ---------------------------------------------------------------------------
#define ATT_ROWS 16
#define ATT_KT   128
#define ATT_SP   2049           /* score row stride (pad) */
#define ATT_QP   68             /* q row stride (pad, 16B aligned) */
#define ATT_SMEM ((ATT_ROWS*ATT_SP + ATT_ROWS*ATT_QP + ATT_KT*64) * sizeof(float))

__global__ void __launch_bounds__(256)
attn_k(const float* __restrict__ QH, const float* __restrict__ KH,
       const float* __restrict__ VH, const int* __restrict__ mask,
       float* __restrict__ OH, float* __restrict__ attn_out, int write_attn)
{
    extern __shared__ float sm[];
    float* sS  = sm;                                  // [16][ATT_SP]
    float* sQ  = sm + ATT_ROWS * ATT_SP;              // [16][ATT_QP]
    float* sKV = sQ + ATT_ROWS * ATT_QP;              // [128][64]

    const int t  = threadIdx.x;
    const int q0 = blockIdx.x * ATT_ROWS;
    const int h  = blockIdx.y;
    const int b  = blockIdx.z;
    const int bh = b * Hc + h;

    // load Q rows (already pre-scaled by 1/sqrt(DK) in projection)
    const float* qbase = QH + ((size_t)bh * Lc + q0) * DKc;
    for (int i = t; i < ATT_ROWS * 16; i += 256) {
        int r = i >> 4, c4 = (i & 15) * 4;
        *(float4*)&sQ[r * ATT_QP + c4] = *(const float4*)&qbase[r * DKc + c4];
    }

    // -------- scores --------
    const int tr = t & 15;        // query row
    const int tc = t >> 4;        // key group (8 keys each)
    // mask is bool in the reference; harness stores it 4 bytes/elem
    // (int32 or float32 — nonzero test is correct for both)
    const int* mrow = mask + ((size_t)b * Lc + (q0 + tr)) * Lc;

    for (int kt = 0; kt < Lc / ATT_KT; kt++) {
        __syncthreads();
        const float* kb = KH + ((size_t)bh * Lc + kt * ATT_KT) * DKc;
        for (int i = t; i < ATT_KT * 16; i += 256) {
            int r = i >> 4, c4 = (i & 15) * 4;
            *(float4*)&sKV[r * 64 + c4] = *(const float4*)&kb[r * DKc + c4];
        }
        __syncthreads();

        float acc[8] = {};
#pragma unroll
        for (int d4 = 0; d4 < 16; d4++) {
            float4 qv = *(const float4*)&sQ[tr * ATT_QP + d4 * 4];
#pragma unroll
            for (int j = 0; j < 8; j++) {
                float4 kv = *(const float4*)&sKV[(tc * 8 + j) * 64 + d4 * 4];
                acc[j] += qv.x * kv.x + qv.y * kv.y + qv.z * kv.z + qv.w * kv.w;
            }
        }
#pragma unroll
        for (int j = 0; j < 8; j++) {
            int k = kt * ATT_KT + tc * 8 + j;
            sS[tr * ATT_SP + k] = (mrow[k] != 0) ? acc[j] : -1e9f;
        }
    }
    __syncthreads();

    // -------- softmax (16 threads / row) --------
    {
        int r = t >> 4, s = t & 15;
        float* row = sS + r * ATT_SP;
        float mx = -3e38f;
        for (int k = s; k < Lc; k += 16) mx = fmaxf(mx, row[k]);
#pragma unroll
        for (int o = 8; o; o >>= 1) mx = fmaxf(mx, __shfl_xor_sync(0xffffffffu, mx, o));
        float sum = 0.f;
        for (int k = s; k < Lc; k += 16) {
            float e = expf(row[k] - mx);
            row[k] = e;
            sum += e;
        }
#pragma unroll
        for (int o = 8; o; o >>= 1) sum += __shfl_xor_sync(0xffffffffu, sum, o);
        float inv = 1.f / sum;
        for (int k = s; k < Lc; k += 16) row[k] *= inv;
    }
    __syncthreads();

    // -------- optional attn output --------
    if (write_attn) {
        for (int r = 0; r < ATT_ROWS; r++) {
            float* dst = attn_out + (((size_t)bh * Lc) + q0 + r) * Lc;
            const float* src = sS + r * ATT_SP;
            for (int k = t; k < Lc; k += 256) dst[k] = src[k];
        }
    }

    // -------- out = P @ V --------
    const int r2 = t >> 4;
    const int d0 = (t & 15) * 4;
    float4 o = {0.f, 0.f, 0.f, 0.f};
    for (int kt = 0; kt < Lc / ATT_KT; kt++) {
        __syncthreads();
        const float* vb = VH + ((size_t)bh * Lc + kt * ATT_KT) * DVc;
        for (int i = t; i < ATT_KT * 16; i += 256) {
            int r = i >> 4, c4 = (i & 15) * 4;
            *(float4*)&sKV[r * 64 + c4] = *(const float4*)&vb[r * DVc + c4];
        }
        __syncthreads();
        const float* prow = sS + r2 * ATT_SP + kt * ATT_KT;
#pragma unroll 4
        for (int kk = 0; kk < ATT_KT; kk++) {
            float p = prow[kk];
            float4 v = *(const float4*)&sKV[kk * 64 + d0];
            o.x += p * v.x; o.y += p * v.y; o.z += p * v.z; o.w += p * v.w;
        }
    }
    *(float4*)&OH[(((size_t)b * Lc + q0 + r2) * Hc + h) * DVc + d0] = o;
}

// ---------------------------------------------------------------------------
// LayerNorm over rows of D=1024. One block (256 thr) per row.
// ---------------------------------------------------------------------------
__global__ void __launch_bounds__(256)
ln_k(const float* __restrict__ X, const float* __restrict__ g,
     const float* __restrict__ bta, float* __restrict__ O)
{
    const int t = threadIdx.x;
    const float* x = X + (size_t)blockIdx.x * Dc;
    float4 v = *(const float4*)&x[t * 4];
    float s  = v.x + v.y + v.z + v.w;
    float s2 = v.x * v.x + v.y * v.y + v.z * v.z + v.w * v.w;
#pragma unroll
    for (int o = 16; o; o >>= 1) {
        s  += __shfl_xor_sync(0xffffffffu, s, o);
        s2 += __shfl_xor_sync(0xffffffffu, s2, o);
    }
    __shared__ float rs[8], rs2[8];
    if ((t & 31) == 0) { rs[t >> 5] = s; rs2[t >> 5] = s2; }
    __syncthreads();
    float S = 0.f, S2 = 0.f;
#pragma unroll
    for (int i = 0; i < 8; i++) { S += rs[i]; S2 += rs2[i]; }
    float mean = S * (1.0f / Dc);
    float var  = S2 * (1.0f / Dc) - mean * mean;
    float inv  = rsqrtf(var + 1e-6f);

    float4 gg = *(const float4*)&g[t * 4];
    float4 bb = *(const float4*)&bta[t * 4];
    float4 r;
    r.x = (v.x - mean) * inv * gg.x + bb.x;
    r.y = (v.y - mean) * inv * gg.y + bb.y;
    r.z = (v.z - mean) * inv * gg.z + bb.z;
    r.w = (v.w - mean) * inv * gg.w + bb.w;
    *(float4*)&O[(size_t)blockIdx.x * Dc + t * 4] = r;
}

// ---------------------------------------------------------------------------
// Launch
// ---------------------------------------------------------------------------
extern "C" void kernel_launch(void* const* d_in, const int* in_sizes, int n_in,
                              void* d_out, int out_size)
{
    const float* q    = (const float*)d_in[0];
    const float* k    = (const float*)d_in[1];
    const float* v    = (const float*)d_in[2];
    const int*   mask = (const int*)d_in[3];
    const float* w_q  = (const float*)d_in[4];
    const float* w_k  = (const float*)d_in[5];
    const float* w_v  = (const float*)d_in[6];
    const float* w_o  = (const float*)d_in[7];
    const float* ln_g = (const float*)d_in[8];
    const float* ln_b = (const float*)d_in[9];
    float* out = (float*)d_out;

    float *pQH, *pKH, *pVH, *pOH, *pOPRE;
    cudaGetSymbolAddress((void**)&pQH,   g_QH);
    cudaGetSymbolAddress((void**)&pKH,   g_KH);
    cudaGetSymbolAddress((void**)&pVH,   g_VH);
    cudaGetSymbolAddress((void**)&pOH,   g_OH);
    cudaGetSymbolAddress((void**)&pOPRE, g_OPRE);

    const long long bld  = (long long)Bc * Lc * Dc;                 // 4194304
    const long long bhll = (long long)Bc * Hc * Lc * Lc;            // 134217728
    int write_attn = ((long long)out_size >= bld + bhll) ? 1 : 0;
    float* attn_out = out + bld;

    // QKV projections (q pre-scaled by 1/sqrt(DK))
    dim3 gg((Dc) / 64, Mrows / 64);   // (16, 64)
    sgemm_k<0><<<gg, 256>>>(q, w_q, pQH, nullptr, 0.125f, Dc, Hc * DKc);
    sgemm_k<0><<<gg, 256>>>(k, w_k, pKH, nullptr, 1.0f,   Dc, Hc * DKc);
    sgemm_k<0><<<gg, 256>>>(v, w_v, pVH, nullptr, 1.0f,   Dc, Hc * DVc);

    // attention
    cudaFuncSetAttribute(attn_k, cudaFuncAttributeMaxDynamicSharedMemorySize,
                         (int)ATT_SMEM);
    dim3 ga(Lc / ATT_ROWS, Hc, Bc);   // (128, 16, 2)
    attn_k<<<ga, 256, ATT_SMEM>>>(pQH, pKH, pVH, mask, pOH, attn_out, write_attn);

    // output projection + residual
    sgemm_k<1><<<gg, 256>>>(pOH, w_o, pOPRE, q, 1.0f, Hc * DVc, Dc);

    // layernorm
    ln_k<<<Mrows, 256>>>(pOPRE, ln_g, ln_b, out);
}

// round 4
// speedup vs baseline: 4.1886x; 4.1886x over previous
#include <cuda_runtime.h>
#include <math.h>
#include <stddef.h>
#include <stdint.h>

// Problem constants
#define Bc 2
#define Lc 2048
#define Dc 1024
#define Hc 16
#define DKc 64
#define DVc 64
#define Mrows (Bc*Lc)            /* 4096 */
#define BHc (Bc*Hc)              /* 32 */

// ---------------------------------------------------------------------------
// Scratch (device globals -- no allocation allowed)
// ---------------------------------------------------------------------------
__device__ __align__(16) float g_QH[(size_t)BHc*Lc*DKc];    // [B,H,L,64]
__device__ __align__(16) float g_KH[(size_t)BHc*Lc*DKc];    // [B,H,L,64]
__device__ __align__(16) float g_VT[(size_t)BHc*DVc*Lc];    // [B,H,64,L]
__device__ __align__(16) float g_S [(size_t)BHc*Lc*Lc];     // [BH,L,L] scores
__device__ __align__(16) float g_OH[(size_t)Mrows*Dc];      // [B,L,H*DV]
__device__ __align__(16) float g_OPRE[(size_t)Mrows*Dc];    // pre-LayerNorm
__device__ __align__(16) float g_WTQ[(size_t)Dc*Dc];
__device__ __align__(16) float g_WTK[(size_t)Dc*Dc];
__device__ __align__(16) float g_WTV[(size_t)Dc*Dc];
__device__ __align__(16) float g_WTO[(size_t)Dc*Dc];

// ---------------------------------------------------------------------------
// tf32 mma.sync helpers (sm_80+ -- works on plain sm_103 target)
// ---------------------------------------------------------------------------
__device__ __forceinline__ uint32_t f2t(float x) {
    uint32_t r;
    asm("cvt.rna.tf32.f32 %0, %1;" : "=r"(r) : "f"(x));
    return r;
}
__device__ __forceinline__ void mma8(float* c, const uint32_t* a, const uint32_t* b) {
    asm volatile(
        "mma.sync.aligned.m16n8k8.row.col.f32.tf32.tf32.f32 "
        "{%0,%1,%2,%3}, {%4,%5,%6,%7}, {%8,%9}, {%0,%1,%2,%3};"
        : "+f"(c[0]), "+f"(c[1]), "+f"(c[2]), "+f"(c[3])
        : "r"(a[0]), "r"(a[1]), "r"(a[2]), "r"(a[3]), "r"(b[0]), "r"(b[1]));
}

// ---------------------------------------------------------------------------
// Warp-MMA tf32 GEMM:  D[128, 64] per block = A[128,KTOT] @ B[64,KTOT]^T
//  A row-major (K-contig), B stored [N,K] (K-contig).
//  256 threads = 8 warps (4x2), warp tile 32x32, BK=32.
// EPI 0: scatter to head layout [B,H,L,64] * scale
// EPI 1: scatter V transposed  [B,H,64,L]
// EPI 2: scores: apply mask, write [z][m][n]            (batched, z=bh)
// EPI 3: PV: write OH[(b*L+m)*1024 + h*64 + n]          (batched)
// EPI 4: out proj: C[m*1024+n] = val + resid[m*1024+n]
// ---------------------------------------------------------------------------
#define SPAD 36   /* smem row stride in u32: frag loads conflict-free */

template<int EPI, int KTOT, int LDA, int LDB>
__global__ void __launch_bounds__(256, 2)
gemm_mma(const float* __restrict__ A, size_t Ab,
         const float* __restrict__ Bp, size_t Bb,
         float* __restrict__ C, const int* __restrict__ mask,
         const float* __restrict__ resid, float scale)
{
    constexpr int NC = KTOT / 32;
    __shared__ uint32_t As[128 * SPAD];
    __shared__ uint32_t Bs[64 * SPAD];

    const int tid  = threadIdx.x;
    const int wid  = tid >> 5, lane = tid & 31;
    const int wm   = wid >> 1, wn = wid & 1;      // warp grid 4x2
    const int g    = lane >> 2, tq = lane & 3;
    const int z    = blockIdx.z;
    const int m0   = blockIdx.y * 128;
    const int n0   = blockIdx.x * 64;
    const float* Az = A  + (size_t)z * Ab;
    const float* Bz = Bp + (size_t)z * Bb;

    // global->reg prefetch indices
    const int ar = tid >> 3, ac4 = (tid & 7) * 4;   // + j*32 rows
    float4 pa[4], pb[2];
    float acc[2][4][4] = {};

    auto g2r = [&](int c) {
        const int kc = c * 32;
#pragma unroll
        for (int j = 0; j < 4; j++)
            pa[j] = *(const float4*)(Az + (size_t)(m0 + ar + j * 32) * LDA + kc + ac4);
#pragma unroll
        for (int j = 0; j < 2; j++)
            pb[j] = *(const float4*)(Bz + (size_t)(n0 + ar + j * 32) * LDB + kc + ac4);
    };
    auto r2s = [&]() {
#pragma unroll
        for (int j = 0; j < 4; j++) {
            uint4 t = { f2t(pa[j].x), f2t(pa[j].y), f2t(pa[j].z), f2t(pa[j].w) };
            *(uint4*)&As[(ar + j * 32) * SPAD + ac4] = t;
        }
#pragma unroll
        for (int j = 0; j < 2; j++) {
            uint4 t = { f2t(pb[j].x), f2t(pb[j].y), f2t(pb[j].z), f2t(pb[j].w) };
            *(uint4*)&Bs[(ar + j * 32) * SPAD + ac4] = t;
        }
    };

    g2r(0);
    for (int c = 0; c < NC; c++) {
        r2s();
        __syncthreads();
        if (c + 1 < NC) g2r(c + 1);       // overlap next gmem load with MMA

#pragma unroll
        for (int ks = 0; ks < 4; ks++) {
            uint32_t af[2][4], bf[4][2];
#pragma unroll
            for (int mi = 0; mi < 2; mi++) {
                int rb = (wm * 32 + mi * 16 + g) * SPAD + ks * 8 + tq;
                af[mi][0] = As[rb];
                af[mi][1] = As[rb + 8 * SPAD];
                af[mi][2] = As[rb + 4];
                af[mi][3] = As[rb + 8 * SPAD + 4];
            }
#pragma unroll
            for (int ni = 0; ni < 4; ni++) {
                int rb = (wn * 32 + ni * 8 + g) * SPAD + ks * 8 + tq;
                bf[ni][0] = Bs[rb];
                bf[ni][1] = Bs[rb + 4];
            }
#pragma unroll
            for (int mi = 0; mi < 2; mi++)
#pragma unroll
                for (int ni = 0; ni < 4; ni++)
                    mma8(acc[mi][ni], af[mi], bf[ni]);
        }
        __syncthreads();
    }

    // -------- epilogue --------
#pragma unroll
    for (int mi = 0; mi < 2; mi++) {
#pragma unroll
        for (int ni = 0; ni < 4; ni++) {
            const float* a = acc[mi][ni];
            int r0  = m0 + wm * 32 + mi * 16 + g;
            int r1  = r0 + 8;
            int col = n0 + wn * 32 + ni * 8 + 2 * tq;

            if (EPI == 0) {
                int h = col >> 6, dk = col & 63;
#pragma unroll
                for (int p = 0; p < 2; p++) {
                    int m = p ? r1 : r0;
                    int b_ = m >> 11, l = m & (Lc - 1);
                    float2 o = { a[2*p] * scale, a[2*p+1] * scale };
                    *(float2*)&C[(((size_t)b_ * Hc + h) * Lc + l) * 64 + dk] = o;
                }
            } else if (EPI == 1) {
                int h = col >> 6, dv = col & 63;
#pragma unroll
                for (int p = 0; p < 2; p++) {
                    int m = p ? r1 : r0;
                    int b_ = m >> 11, l = m & (Lc - 1);
                    size_t base = ((size_t)b_ * Hc + h) * 64;
                    C[(base + dv)     * Lc + l] = a[2*p];
                    C[(base + dv + 1) * Lc + l] = a[2*p+1];
                }
            } else if (EPI == 2) {
                int b_ = z >> 4;
#pragma unroll
                for (int p = 0; p < 2; p++) {
                    int m = p ? r1 : r0;
                    int2 mm = *(const int2*)&mask[((size_t)b_ * Lc + m) * Lc + col];
                    float2 o;
                    o.x = mm.x ? a[2*p]   : -1e9f;
                    o.y = mm.y ? a[2*p+1] : -1e9f;
                    *(float2*)&C[((size_t)z * Lc + m) * Lc + col] = o;
                }
            } else if (EPI == 3) {
                int b_ = z >> 4, h = z & 15;
#pragma unroll
                for (int p = 0; p < 2; p++) {
                    int m = p ? r1 : r0;
                    float2 o = { a[2*p], a[2*p+1] };
                    *(float2*)&C[((size_t)b_ * Lc + m) * Dc + h * 64 + col] = o;
                }
            } else {   // EPI 4
#pragma unroll
                for (int p = 0; p < 2; p++) {
                    int m = p ? r1 : r0;
                    size_t off = (size_t)m * Dc + col;
                    float2 r4 = *(const float2*)&resid[off];
                    float2 o = { a[2*p] + r4.x, a[2*p+1] + r4.y };
                    *(float2*)&C[off] = o;
                }
            }
        }
    }
}

// ---------------------------------------------------------------------------
// 1024x1024 transpose: out[n][k] = in[k][n]
// ---------------------------------------------------------------------------
__global__ void __launch_bounds__(256)
transpose_k(const float* __restrict__ in, float* __restrict__ out)
{
    __shared__ float t[32][33];
    int x = blockIdx.x * 32 + threadIdx.x;
    int y0 = blockIdx.y * 32;
#pragma unroll
    for (int j = 0; j < 4; j++)
        t[threadIdx.y + j * 8][threadIdx.x] = in[(size_t)(y0 + threadIdx.y + j * 8) * 1024 + x];
    __syncthreads();
    int x2 = blockIdx.y * 32 + threadIdx.x;
    int y2 = blockIdx.x * 32;
#pragma unroll
    for (int j = 0; j < 4; j++)
        out[(size_t)(y2 + threadIdx.y + j * 8) * 1024 + x2] = t[threadIdx.x][threadIdx.y + j * 8];
}

// ---------------------------------------------------------------------------
// Row softmax over [rows, 2048]  (in/out may alias)
// ---------------------------------------------------------------------------
__global__ void __launch_bounds__(256)
softmax_k(const float* __restrict__ S, float* __restrict__ P)
{
    __shared__ float red[8];
    const int t = threadIdx.x;
    const size_t base = (size_t)blockIdx.x * Lc;
    const float4* sp = (const float4*)(S + base);
    float4 x0 = sp[t], x1 = sp[t + 256];

    float mx = fmaxf(fmaxf(fmaxf(x0.x, x0.y), fmaxf(x0.z, x0.w)),
                     fmaxf(fmaxf(x1.x, x1.y), fmaxf(x1.z, x1.w)));
#pragma unroll
    for (int o = 16; o; o >>= 1) mx = fmaxf(mx, __shfl_xor_sync(0xffffffffu, mx, o));
    if ((t & 31) == 0) red[t >> 5] = mx;
    __syncthreads();
    float M = fmaxf(fmaxf(fmaxf(red[0], red[1]), fmaxf(red[2], red[3])),
                    fmaxf(fmaxf(red[4], red[5]), fmaxf(red[6], red[7])));
    __syncthreads();

    x0.x = expf(x0.x - M); x0.y = expf(x0.y - M);
    x0.z = expf(x0.z - M); x0.w = expf(x0.w - M);
    x1.x = expf(x1.x - M); x1.y = expf(x1.y - M);
    x1.z = expf(x1.z - M); x1.w = expf(x1.w - M);

    float s = x0.x + x0.y + x0.z + x0.w + x1.x + x1.y + x1.z + x1.w;
#pragma unroll
    for (int o = 16; o; o >>= 1) s += __shfl_xor_sync(0xffffffffu, s, o);
    if ((t & 31) == 0) red[t >> 5] = s;
    __syncthreads();
    float Ssum = red[0] + red[1] + red[2] + red[3] + red[4] + red[5] + red[6] + red[7];
    float inv = 1.0f / Ssum;

    float4* pp = (float4*)(P + base);
    x0.x *= inv; x0.y *= inv; x0.z *= inv; x0.w *= inv;
    x1.x *= inv; x1.y *= inv; x1.z *= inv; x1.w *= inv;
    pp[t] = x0; pp[t + 256] = x1;
}

// ---------------------------------------------------------------------------
// LayerNorm over rows of D=1024
// ---------------------------------------------------------------------------
__global__ void __launch_bounds__(256)
ln_k(const float* __restrict__ X, const float* __restrict__ g,
     const float* __restrict__ bta, float* __restrict__ O)
{
    const int t = threadIdx.x;
    const float* x = X + (size_t)blockIdx.x * Dc;
    float4 v = *(const float4*)&x[t * 4];
    float s  = v.x + v.y + v.z + v.w;
    float s2 = v.x * v.x + v.y * v.y + v.z * v.z + v.w * v.w;
#pragma unroll
    for (int o = 16; o; o >>= 1) {
        s  += __shfl_xor_sync(0xffffffffu, s, o);
        s2 += __shfl_xor_sync(0xffffffffu, s2, o);
    }
    __shared__ float rs[8], rs2[8];
    if ((t & 31) == 0) { rs[t >> 5] = s; rs2[t >> 5] = s2; }
    __syncthreads();
    float S = 0.f, S2 = 0.f;
#pragma unroll
    for (int i = 0; i < 8; i++) { S += rs[i]; S2 += rs2[i]; }
    float mean = S * (1.0f / Dc);
    float var  = S2 * (1.0f / Dc) - mean * mean;
    float inv  = rsqrtf(var + 1e-6f);

    float4 gg = *(const float4*)&g[t * 4];
    float4 bb = *(const float4*)&bta[t * 4];
    float4 r;
    r.x = (v.x - mean) * inv * gg.x + bb.x;
    r.y = (v.y - mean) * inv * gg.y + bb.y;
    r.z = (v.z - mean) * inv * gg.z + bb.z;
    r.w = (v.w - mean) * inv * gg.w + bb.w;
    *(float4*)&O[(size_t)blockIdx.x * Dc + t * 4] = r;
}

// ---------------------------------------------------------------------------
// Launch
// ---------------------------------------------------------------------------
extern "C" void kernel_launch(void* const* d_in, const int* in_sizes, int n_in,
                              void* d_out, int out_size)
{
    const float* q    = (const float*)d_in[0];
    const float* k    = (const float*)d_in[1];
    const float* v    = (const float*)d_in[2];
    const int*   mask = (const int*)d_in[3];
    const float* w_q  = (const float*)d_in[4];
    const float* w_k  = (const float*)d_in[5];
    const float* w_v  = (const float*)d_in[6];
    const float* w_o  = (const float*)d_in[7];
    const float* ln_g = (const float*)d_in[8];
    const float* ln_b = (const float*)d_in[9];
    float* out = (float*)d_out;

    float *pQH, *pKH, *pVT, *pS, *pOH, *pOPRE, *pWTQ, *pWTK, *pWTV, *pWTO;
    cudaGetSymbolAddress((void**)&pQH,   g_QH);
    cudaGetSymbolAddress((void**)&pKH,   g_KH);
    cudaGetSymbolAddress((void**)&pVT,   g_VT);
    cudaGetSymbolAddress((void**)&pS,    g_S);
    cudaGetSymbolAddress((void**)&pOH,   g_OH);
    cudaGetSymbolAddress((void**)&pOPRE, g_OPRE);
    cudaGetSymbolAddress((void**)&pWTQ,  g_WTQ);
    cudaGetSymbolAddress((void**)&pWTK,  g_WTK);
    cudaGetSymbolAddress((void**)&pWTV,  g_WTV);
    cudaGetSymbolAddress((void**)&pWTO,  g_WTO);

    const long long bld  = (long long)Bc * Lc * Dc;
    const long long bhll = (long long)BHc * Lc * Lc;
    int write_attn = ((long long)out_size >= bld + bhll) ? 1 : 0;
    float* pv_src = write_attn ? (out + bld) : pS;   // softmax dst == PV src

    // 1) weight transposes -> [N,K] B operands
    dim3 tb(32, 8), tg(32, 32);
    transpose_k<<<tg, tb>>>(w_q, pWTQ);
    transpose_k<<<tg, tb>>>(w_k, pWTK);
    transpose_k<<<tg, tb>>>(w_v, pWTV);
    transpose_k<<<tg, tb>>>(w_o, pWTO);

    // 2) projections (q pre-scaled by 1/sqrt(DK))
    dim3 gp(16, 32, 1);
    gemm_mma<0,1024,1024,1024><<<gp, 256>>>(q, 0, pWTQ, 0, pQH, nullptr, nullptr, 0.125f);
    gemm_mma<0,1024,1024,1024><<<gp, 256>>>(k, 0, pWTK, 0, pKH, nullptr, nullptr, 1.0f);
    gemm_mma<1,1024,1024,1024><<<gp, 256>>>(v, 0, pWTV, 0, pVT, nullptr, nullptr, 1.0f);

    // 3) scores = qh @ kh^T with fused mask epilogue
    dim3 gs(32, 16, BHc);
    gemm_mma<2,64,64,64><<<gs, 256>>>(pQH, (size_t)Lc*DKc, pKH, (size_t)Lc*DKc,
                                      pS, mask, nullptr, 1.0f);

    // 4) softmax (writes attn directly into output region when required)
    softmax_k<<<BHc * Lc, 256>>>(pS, pv_src);

    // 5) out = attn @ V
    dim3 gpv(1, 16, BHc);
    gemm_mma<3,2048,2048,2048><<<gpv, 256>>>(pv_src, (size_t)Lc*Lc, pVT, (size_t)DVc*Lc,
                                             pOH, nullptr, nullptr, 1.0f);

    // 6) output projection + residual
    gemm_mma<4,1024,1024,1024><<<gp, 256>>>(pOH, 0, pWTO, 0, pOPRE, nullptr, q, 1.0f);

    // 7) layernorm
    ln_k<<<Mrows, 256>>>(pOPRE, ln_g, ln_b, out);
}